// round 1
// baseline (speedup 1.0000x reference)
#include <cuda_runtime.h>
#include <math.h>

#define L_ 4
#define H_ 12
#define C_ 768
#define HS_ 64
#define HID_ 2048
#define V_ 32000
#define B_ 2
#define T_ 2048
#define BT_ (B_*T_)

// ---------------- scratch (static device globals; no allocation) ----------------
__device__ float g_x[BT_*C_];            // residual stream   [B*T, C]
__device__ float g_h[BT_*C_];            // layernorm output  [B*T, C]
__device__ float g_q[B_*H_*T_*HS_];      // [B,H,T,HS]
__device__ float g_k[B_*H_*T_*HS_];
__device__ float g_v[B_*H_*T_*HS_];
__device__ float g_hh[(size_t)BT_*HID_]; // fc1 out [B*T, HID]
__device__ float g_g[BT_*(HID_/2)];      // gated   [B*T, HID/2]

// ---------------- embedding: x = tok_emb[idx] + pos_emb[t] ----------------
__global__ void embed_k(const int* __restrict__ idx,
                        const float* __restrict__ tok,
                        const float* __restrict__ pos) {
    int m = blockIdx.x;            // row in [0, B*T)
    int t = m % T_;
    int id = idx[m];
    const float* tr = tok + (size_t)id * C_;
    const float* pr = pos + (size_t)t  * C_;
    float* xr = g_x + (size_t)m * C_;
    for (int c = threadIdx.x; c < C_; c += blockDim.x)
        xr[c] = tr[c] + pr[c];
}

// ---------------- layernorm: g_h = LN(g_x) * g + b ----------------
__global__ void ln_k(const float* __restrict__ gg, const float* __restrict__ bb) {
    int m = blockIdx.x;
    const float* row = g_x + (size_t)m * C_;
    float s = 0.f, s2 = 0.f;
    for (int c = threadIdx.x; c < C_; c += 256) {
        float v = row[c]; s += v; s2 += v * v;
    }
    #pragma unroll
    for (int o = 16; o; o >>= 1) {
        s  += __shfl_xor_sync(0xffffffffu, s,  o);
        s2 += __shfl_xor_sync(0xffffffffu, s2, o);
    }
    __shared__ float sh[16];
    int wid = threadIdx.x >> 5, lane = threadIdx.x & 31;
    if (lane == 0) { sh[wid] = s; sh[8 + wid] = s2; }
    __syncthreads();
    if (threadIdx.x == 0) {
        float ts = 0.f, ts2 = 0.f;
        #pragma unroll
        for (int w = 0; w < 8; w++) { ts += sh[w]; ts2 += sh[8 + w]; }
        sh[0] = ts; sh[8] = ts2;
    }
    __syncthreads();
    float mean = sh[0] * (1.f / C_);
    float var  = sh[8] * (1.f / C_) - mean * mean;
    float inv  = rsqrtf(var + 1e-5f);
    float* orow = g_h + (size_t)m * C_;
    for (int c = threadIdx.x; c < C_; c += 256)
        orow[c] = (row[c] - mean) * inv * gg[c] + bb[c];
}

// ---------------- per-head projection: out[b,h,t,:] = g_h[b,t,:] @ W[h] ----------------
// W: per-layer base, heads strided by C_*HS_. Grid: (BT/64, H), block (16,16).
__global__ void gemm_qkv_k(const float* __restrict__ W, float* __restrict__ out) {
    int h  = blockIdx.y;
    const float* Bm = W + (size_t)h * C_ * HS_;   // [C, 64] row-major, ldb=64
    int m0 = blockIdx.x * 64;
    __shared__ float As[16][68];   // transposed A tile: [k][m], row pad -> 272B rows
    __shared__ float Bs[16][64];
    int tx = threadIdx.x, ty = threadIdx.y;
    int tid = ty * 16 + tx;
    int arow = tid >> 2, ac4 = tid & 3;    // A tile: 64 rows x 16 cols, float4 per thread
    int brow = tid >> 4, bc4 = tid & 15;   // B tile: 16 rows x 64 cols
    float acc[4][4] = {};
    for (int k0 = 0; k0 < C_; k0 += 16) {
        float4 av = *(const float4*)(g_h + (size_t)(m0 + arow) * C_ + k0 + ac4 * 4);
        As[ac4*4+0][arow] = av.x; As[ac4*4+1][arow] = av.y;
        As[ac4*4+2][arow] = av.z; As[ac4*4+3][arow] = av.w;
        *(float4*)&Bs[brow][bc4*4] = *(const float4*)(Bm + (size_t)(k0 + brow) * HS_ + bc4 * 4);
        __syncthreads();
        #pragma unroll
        for (int kk = 0; kk < 16; kk++) {
            float4 a = *(const float4*)&As[kk][ty * 4];
            float4 b = *(const float4*)&Bs[kk][tx * 4];
            acc[0][0] += a.x*b.x; acc[0][1] += a.x*b.y; acc[0][2] += a.x*b.z; acc[0][3] += a.x*b.w;
            acc[1][0] += a.y*b.x; acc[1][1] += a.y*b.y; acc[1][2] += a.y*b.z; acc[1][3] += a.y*b.w;
            acc[2][0] += a.z*b.x; acc[2][1] += a.z*b.y; acc[2][2] += a.z*b.z; acc[2][3] += a.z*b.w;
            acc[3][0] += a.w*b.x; acc[3][1] += a.w*b.y; acc[3][2] += a.w*b.z; acc[3][3] += a.w*b.w;
        }
        __syncthreads();
    }
    #pragma unroll
    for (int i = 0; i < 4; i++) {
        int m = m0 + ty * 4 + i;
        int bidx = m / T_, t = m % T_;
        float* orow = out + (((size_t)(bidx * H_ + h) * T_ + t) * HS_);
        #pragma unroll
        for (int j = 0; j < 4; j++) orow[tx * 4 + j] = acc[i][j];
    }
}

// ---------------- generic SGEMM: C = A[MxK] @ B[KxN] (+bias) (+=residual) ----------------
// EPI: 0 = store, 1 = store + bias, 2 = C += acc + bias
template<int EPI>
__global__ void sgemm_k(const float* __restrict__ A, const float* __restrict__ Bm,
                        float* __restrict__ C, const float* __restrict__ bias,
                        int M, int N, int K) {
    int n0 = blockIdx.x * 64, m0 = blockIdx.y * 64;
    __shared__ float As[16][68];
    __shared__ float Bs[16][64];
    int tx = threadIdx.x, ty = threadIdx.y;
    int tid = ty * 16 + tx;
    int arow = tid >> 2, ac4 = tid & 3;
    int brow = tid >> 4, bc4 = tid & 15;
    float acc[4][4] = {};
    for (int k0 = 0; k0 < K; k0 += 16) {
        float4 av = *(const float4*)(A + (size_t)(m0 + arow) * K + k0 + ac4 * 4);
        As[ac4*4+0][arow] = av.x; As[ac4*4+1][arow] = av.y;
        As[ac4*4+2][arow] = av.z; As[ac4*4+3][arow] = av.w;
        *(float4*)&Bs[brow][bc4*4] = *(const float4*)(Bm + (size_t)(k0 + brow) * N + n0 + bc4 * 4);
        __syncthreads();
        #pragma unroll
        for (int kk = 0; kk < 16; kk++) {
            float4 a = *(const float4*)&As[kk][ty * 4];
            float4 b = *(const float4*)&Bs[kk][tx * 4];
            acc[0][0] += a.x*b.x; acc[0][1] += a.x*b.y; acc[0][2] += a.x*b.z; acc[0][3] += a.x*b.w;
            acc[1][0] += a.y*b.x; acc[1][1] += a.y*b.y; acc[1][2] += a.y*b.z; acc[1][3] += a.y*b.w;
            acc[2][0] += a.z*b.x; acc[2][1] += a.z*b.y; acc[2][2] += a.z*b.z; acc[2][3] += a.z*b.w;
            acc[3][0] += a.w*b.x; acc[3][1] += a.w*b.y; acc[3][2] += a.w*b.z; acc[3][3] += a.w*b.w;
        }
        __syncthreads();
    }
    #pragma unroll
    for (int i = 0; i < 4; i++) {
        int m = m0 + ty * 4 + i;
        #pragma unroll
        for (int j = 0; j < 4; j++) {
            int n = n0 + tx * 4 + j;
            size_t idxo = (size_t)m * N + n;
            float val = acc[i][j];
            if (EPI >= 1) val += bias[n];
            if (EPI == 2) C[idxo] += val;
            else          C[idxo]  = val;
        }
    }
}

// ---------------- fused causal attention with decay bias, online softmax ----------------
// q,k,v: [B,H,T,HS]. One warp per query row; 8 warps/block; K/V chunk of 32 keys in SMEM.
// Writes  x[b, t, h*HS + d] += softmax(q k^T * scale + |dc|*(s-t)) @ v   (residual add)
__global__ void attn_k(const float* __restrict__ q, const float* __restrict__ k,
                       const float* __restrict__ v, const float* __restrict__ decay,
                       float* __restrict__ x) {
    int bh = blockIdx.y;
    int b  = bh / H_, h = bh % H_;
    int wid = threadIdx.x >> 5, lane = threadIdx.x & 31;
    int r = blockIdx.x * 8 + wid;                 // query row
    float dcv = fabsf(decay[h]);
    const float* qrow = q + ((size_t)bh * T_ + r) * HS_;
    float q0 = qrow[lane], q1 = qrow[lane + 32];
    const float* kb = k + (size_t)bh * T_ * HS_;
    const float* vb = v + (size_t)bh * T_ * HS_;
    __shared__ float ks[32][64];
    __shared__ float vs[32][64];
    float mx = -1e30f, lsum = 0.f, a0 = 0.f, a1 = 0.f;
    int rmax = blockIdx.x * 8 + 7;
    for (int c0 = 0; c0 <= rmax; c0 += 32) {
        __syncthreads();
        for (int i = threadIdx.x; i < 32 * 16; i += 256) {  // float4 units
            int row = i >> 4, col4 = i & 15;
            ((float4*)ks[row])[col4] = ((const float4*)(kb + (size_t)(c0 + row) * HS_))[col4];
            ((float4*)vs[row])[col4] = ((const float4*)(vb + (size_t)(c0 + row) * HS_))[col4];
        }
        __syncthreads();
        int send = r - c0; if (send > 31) send = 31;
        for (int si = 0; si <= send; si++) {
            float sc = q0 * ks[si][lane] + q1 * ks[si][lane + 32];
            #pragma unroll
            for (int o = 16; o; o >>= 1) sc += __shfl_xor_sync(0xffffffffu, sc, o);
            int s = c0 + si;
            float xsc = sc * 0.125f + dcv * (float)(s - r);   // s<=r -> bias<=0
            float nm  = fmaxf(mx, xsc);
            float esc = __expf(mx - nm);
            float e   = __expf(xsc - nm);
            lsum = lsum * esc + e;
            a0   = a0 * esc + e * vs[si][lane];
            a1   = a1 * esc + e * vs[si][lane + 32];
            mx = nm;
        }
    }
    float inv = 1.f / lsum;
    float* xr = x + ((size_t)(b * T_ + r)) * C_ + h * HS_;
    xr[lane]      += a0 * inv;
    xr[lane + 32] += a1 * inv;
}

// ---------------- SiLU gate: g_g = hh[:, :1024] * silu(hh[:, 1024:]) ----------------
__global__ void gate_k() {
    int i = blockIdx.x * 256 + threadIdx.x;          // over BT_*1024
    int m = i >> 10, j = i & 1023;
    float xv = g_hh[(size_t)m * HID_ + j];
    float xg = g_hh[(size_t)m * HID_ + 1024 + j];
    float sg = 1.f / (1.f + __expf(-xg));
    g_g[i] = xv * (xg * sg);
}

// ---------------- host launch ----------------
extern "C" void kernel_launch(void* const* d_in, const int* in_sizes, int n_in,
                              void* d_out, int out_size) {
    const int*   idx  = (const int*)  d_in[0];
    const float* tok  = (const float*)d_in[1];
    const float* pos  = (const float*)d_in[2];
    const float* Wq   = (const float*)d_in[3];
    const float* Wk   = (const float*)d_in[4];
    const float* Wv   = (const float*)d_in[5];
    const float* dcy  = (const float*)d_in[6];
    const float* ln1g = (const float*)d_in[7];
    const float* ln1b = (const float*)d_in[8];
    const float* fc1w = (const float*)d_in[9];
    const float* fc1b = (const float*)d_in[10];
    const float* fc2w = (const float*)d_in[11];
    const float* fc2b = (const float*)d_in[12];
    const float* ln2g = (const float*)d_in[13];
    const float* ln2b = (const float*)d_in[14];
    const float* lnfg = (const float*)d_in[15];
    const float* lnfb = (const float*)d_in[16];
    const float* lmw  = (const float*)d_in[17];
    float* out = (float*)d_out;

    float *ph, *pq, *pk, *pv, *phh, *pg, *px;
    cudaGetSymbolAddress((void**)&px,  g_x);
    cudaGetSymbolAddress((void**)&ph,  g_h);
    cudaGetSymbolAddress((void**)&pq,  g_q);
    cudaGetSymbolAddress((void**)&pk,  g_k);
    cudaGetSymbolAddress((void**)&pv,  g_v);
    cudaGetSymbolAddress((void**)&phh, g_hh);
    cudaGetSymbolAddress((void**)&pg,  g_g);

    dim3 thr(16, 16);
    embed_k<<<BT_, 256>>>(idx, tok, pos);
    for (int l = 0; l < L_; l++) {
        ln_k<<<BT_, 256>>>(ln1g + l * C_, ln1b + l * C_);
        size_t woff = (size_t)l * H_ * C_ * HS_;
        gemm_qkv_k<<<dim3(BT_/64, H_), thr>>>(Wq + woff, pq);
        gemm_qkv_k<<<dim3(BT_/64, H_), thr>>>(Wk + woff, pk);
        gemm_qkv_k<<<dim3(BT_/64, H_), thr>>>(Wv + woff, pv);
        attn_k<<<dim3(T_/8, B_*H_), 256>>>(pq, pk, pv, dcy + l * H_, px);
        ln_k<<<BT_, 256>>>(ln2g + l * C_, ln2b + l * C_);
        sgemm_k<1><<<dim3(HID_/64, BT_/64), thr>>>(ph, fc1w + (size_t)l * C_ * HID_, phh,
                                                   fc1b + l * HID_, BT_, HID_, C_);
        gate_k<<<(BT_ * (HID_/2)) / 256, 256>>>();
        sgemm_k<2><<<dim3(C_/64, BT_/64), thr>>>(pg, fc2w + (size_t)l * (HID_/2) * C_, px,
                                                 fc2b + l * C_, BT_, C_, HID_/2);
    }
    ln_k<<<BT_, 256>>>(lnfg, lnfb);
    sgemm_k<0><<<dim3(V_/64, BT_/64), thr>>>(ph, lmw, out, nullptr, BT_, V_, C_);
}

// round 4
// speedup vs baseline: 1.6669x; 1.6669x over previous
#include <cuda_runtime.h>
#include <cuda_fp16.h>
#include <cstdint>
#include <math.h>

#define L_ 4
#define H_ 12
#define C_ 768
#define HS_ 64
#define HID_ 2048
#define V_ 32000
#define B_ 2
#define T_ 2048
#define BT_ (B_*T_)

// ---------------- scratch (static device globals; no allocation) ----------------
__device__ float  g_x[BT_*C_];             // residual stream   [B*T, C] fp32
__device__ __half g_h16[BT_*C_];           // layernorm out fp16
__device__ float  g_q[B_*H_*T_*HS_];       // [B,H,T,HS] fp32 (attention path)
__device__ float  g_k[B_*H_*T_*HS_];
__device__ float  g_v[B_*H_*T_*HS_];
__device__ float  g_hh[(size_t)BT_*HID_];  // fc1 out fp32
__device__ __half g_g16[BT_*(HID_/2)];     // gated fp16
// fp16 weights (converted each launch; deterministic)
__device__ __half w_qkv16[(size_t)L_*C_*3*H_*HS_];   // [L][C][2304] packed q|k|v
__device__ __half w_fc1[(size_t)L_*C_*HID_];
__device__ __half w_fc2[(size_t)L_*(HID_/2)*C_];
__device__ __half w_lm[(size_t)C_*V_];

__device__ __forceinline__ unsigned int smem_u32(const void* p) {
    unsigned int a;
    asm("{ .reg .u64 t; cvta.to.shared.u64 t, %1; cvt.u32.u64 %0, t; }" : "=r"(a) : "l"(p));
    return a;
}

// ---------------- fp32 -> fp16 bulk convert (vectorized) ----------------
__global__ void f2h4_k(const float* __restrict__ s, __half* __restrict__ d, int n4) {
    int i = blockIdx.x * 256 + threadIdx.x;
    if (i >= n4) return;
    float4 f = ((const float4*)s)[i];
    ((half2*)d)[2*i]     = __floats2half2_rn(f.x, f.y);
    ((half2*)d)[2*i + 1] = __floats2half2_rn(f.z, f.w);
}

// ---------------- pack Wq/Wk/Wv [L,H,C,HS] -> [L][C][3*H*HS] fp16 ----------------
__global__ void qkvpack_k(const float* __restrict__ Wq, const float* __restrict__ Wk,
                          const float* __restrict__ Wv) {
    int i = blockIdx.x * 256 + threadIdx.x;     // over L*H*C*HS
    if (i >= L_*H_*C_*HS_) return;
    int d = i % HS_; int tmp = i / HS_;
    int c = tmp % C_; tmp /= C_;
    int h = tmp % H_; int l = tmp / H_;
    size_t src = (((size_t)l*H_ + h)*C_ + c)*HS_ + d;
    size_t dst = ((size_t)l*C_ + c)*(3*H_*HS_) + h*HS_ + d;
    w_qkv16[dst           ] = __float2half(Wq[src]);
    w_qkv16[dst +   H_*HS_] = __float2half(Wk[src]);
    w_qkv16[dst + 2*H_*HS_] = __float2half(Wv[src]);
}

// ---------------- embedding ----------------
__global__ void embed_k(const int* __restrict__ idx,
                        const float* __restrict__ tok,
                        const float* __restrict__ pos) {
    int m = blockIdx.x;
    int t = m % T_;
    int id = idx[m];
    const float* tr = tok + (size_t)id * C_;
    const float* pr = pos + (size_t)t  * C_;
    float* xr = g_x + (size_t)m * C_;
    for (int c = threadIdx.x; c < C_; c += blockDim.x)
        xr[c] = tr[c] + pr[c];
}

// ---------------- layernorm -> fp16 ----------------
__global__ void ln_k(const float* __restrict__ gg, const float* __restrict__ bb) {
    int m = blockIdx.x;
    const float* row = g_x + (size_t)m * C_;
    float s = 0.f, s2 = 0.f;
    for (int c = threadIdx.x; c < C_; c += 256) {
        float v = row[c]; s += v; s2 += v * v;
    }
    #pragma unroll
    for (int o = 16; o; o >>= 1) {
        s  += __shfl_xor_sync(0xffffffffu, s,  o);
        s2 += __shfl_xor_sync(0xffffffffu, s2, o);
    }
    __shared__ float sh[16];
    int wid = threadIdx.x >> 5, lane = threadIdx.x & 31;
    if (lane == 0) { sh[wid] = s; sh[8 + wid] = s2; }
    __syncthreads();
    if (threadIdx.x == 0) {
        float ts = 0.f, ts2 = 0.f;
        #pragma unroll
        for (int w = 0; w < 8; w++) { ts += sh[w]; ts2 += sh[8 + w]; }
        sh[0] = ts; sh[8] = ts2;
    }
    __syncthreads();
    float mean = sh[0] * (1.f / C_);
    float var  = sh[8] * (1.f / C_) - mean * mean;
    float inv  = rsqrtf(var + 1e-5f);
    __half* orow = g_h16 + (size_t)m * C_;
    for (int c = threadIdx.x; c < C_; c += 256)
        orow[c] = __float2half((row[c] - mean) * inv * gg[c] + bb[c]);
}

// ---------------- HGEMM: C[MxN] = A[MxK](fp16) @ B[KxN](fp16), fp32 accum ----------------
// EPI 0: C=acc   1: C=acc+bias   2: C+=acc+bias (residual)   3: QKV scatter to q/k/v
template<int EPI>
__global__ __launch_bounds__(256, 2)
void hgemm_k(const __half* __restrict__ A, const __half* __restrict__ Bw,
             float* __restrict__ C, const float* __restrict__ bias,
             int M, int N, int K,
             float* __restrict__ qo, float* __restrict__ ko, float* __restrict__ vo) {
    __shared__ __half As[128][40];    // m-major, k contiguous, pad 8
    __shared__ __half Bs[32][136];    // k-major, n contiguous, pad 8
    const int tid  = threadIdx.x;
    const int lane = tid & 31;
    const int wid  = tid >> 5;
    const int wm = (wid & 1) * 64;    // warp row offset (2 x 64)
    const int wn = (wid >> 1) * 32;   // warp col offset (4 x 32)
    const int m0 = blockIdx.y * 128;
    const int n0 = blockIdx.x * 128;

    float acc[4][4][4];
    #pragma unroll
    for (int i = 0; i < 4; i++)
        #pragma unroll
        for (int j = 0; j < 4; j++)
            acc[i][j][0] = acc[i][j][1] = acc[i][j][2] = acc[i][j][3] = 0.f;

    const int arow = tid >> 1, aseg = (tid & 1) * 16;  // 2 x uint4 per thread
    const int brow = tid >> 3, bseg = (tid & 7) * 16;  // 2 x uint4 per thread

    for (int k0 = 0; k0 < K; k0 += 32) {
        const uint4* asrc = (const uint4*)(A + (size_t)(m0 + arow) * K + k0 + aseg);
        uint4 av0 = asrc[0], av1 = asrc[1];
        const uint4* bsrc = (const uint4*)(Bw + (size_t)(k0 + brow) * N + n0 + bseg);
        uint4 bv0 = bsrc[0], bv1 = bsrc[1];
        *(uint4*)&As[arow][aseg]     = av0;
        *(uint4*)&As[arow][aseg + 8] = av1;
        *(uint4*)&Bs[brow][bseg]     = bv0;
        *(uint4*)&Bs[brow][bseg + 8] = bv1;
        __syncthreads();
        #pragma unroll
        for (int kk = 0; kk < 32; kk += 16) {
            unsigned int af[4][4], bf[4][2];
            #pragma unroll
            for (int i = 0; i < 4; i++) {
                unsigned int p = smem_u32(&As[wm + i*16 + (lane & 7) + ((lane >> 3) & 1) * 8]
                                            [kk + (lane >> 4) * 8]);
                asm volatile("ldmatrix.sync.aligned.m8n8.x4.shared.b16 {%0,%1,%2,%3}, [%4];"
                             : "=r"(af[i][0]), "=r"(af[i][1]), "=r"(af[i][2]), "=r"(af[i][3])
                             : "r"(p));
            }
            #pragma unroll
            for (int j = 0; j < 4; j++) {
                unsigned int p = smem_u32(&Bs[kk + (lane & 15)][wn + j*8]);
                asm volatile("ldmatrix.sync.aligned.m8n8.x2.trans.shared.b16 {%0,%1}, [%2];"
                             : "=r"(bf[j][0]), "=r"(bf[j][1]) : "r"(p));
            }
            #pragma unroll
            for (int i = 0; i < 4; i++)
                #pragma unroll
                for (int j = 0; j < 4; j++)
                    asm volatile(
                        "mma.sync.aligned.m16n8k16.row.col.f32.f16.f16.f32 "
                        "{%0,%1,%2,%3}, {%4,%5,%6,%7}, {%8,%9}, {%0,%1,%2,%3};"
                        : "+f"(acc[i][j][0]), "+f"(acc[i][j][1]),
                          "+f"(acc[i][j][2]), "+f"(acc[i][j][3])
                        : "r"(af[i][0]), "r"(af[i][1]), "r"(af[i][2]), "r"(af[i][3]),
                          "r"(bf[j][0]), "r"(bf[j][1]));
        }
        __syncthreads();
    }

    const int mrow = lane >> 2, ncol = (lane & 3) * 2;
    if (EPI == 3) {
        // n0 block lies entirely within one of q/k/v (768 % 128 == 0)
        const int which = n0 / (H_*HS_);
        float* dst = (which == 0) ? qo : (which == 1) ? ko : vo;
        const int nbase = n0 - which * (H_*HS_);
        #pragma unroll
        for (int i = 0; i < 4; i++) {
            int m = m0 + wm + i*16 + mrow;
            int b = m >> 11, t = m & (T_-1);
            #pragma unroll
            for (int j = 0; j < 4; j++) {
                int r = nbase + wn + j*8 + ncol;
                int h = r >> 6, d = r & 63;
                size_t o = (((size_t)(b*H_ + h))*T_ + t)*HS_ + d;
                dst[o]           = acc[i][j][0];
                dst[o + 1]       = acc[i][j][1];
                dst[o + 8*HS_]   = acc[i][j][2];   // t+8, same b/h
                dst[o + 8*HS_+1] = acc[i][j][3];
            }
        }
    } else {
        #pragma unroll
        for (int i = 0; i < 4; i++) {
            int m = m0 + wm + i*16 + mrow;
            #pragma unroll
            for (int j = 0; j < 4; j++) {
                int n = n0 + wn + j*8 + ncol;
                size_t o = (size_t)m * N + n;
                float v0 = acc[i][j][0], v1 = acc[i][j][1];
                float v2 = acc[i][j][2], v3 = acc[i][j][3];
                if (EPI >= 1) { float b0 = bias[n], b1 = bias[n+1];
                                v0 += b0; v1 += b1; v2 += b0; v3 += b1; }
                if (EPI == 2) {
                    C[o]       += v0; C[o+1]       += v1;
                    C[o+8*(size_t)N] += v2; C[o+8*(size_t)N+1] += v3;
                } else {
                    C[o]       = v0; C[o+1]       = v1;
                    C[o+8*(size_t)N] = v2; C[o+8*(size_t)N+1] = v3;
                }
            }
        }
    }
}

// ---------------- fused causal attention (fp32, online softmax) ----------------
__global__ void attn_k(const float* __restrict__ q, const float* __restrict__ k,
                       const float* __restrict__ v, const float* __restrict__ decay,
                       float* __restrict__ x) {
    int bh = blockIdx.y;
    int b  = bh / H_, h = bh % H_;
    int wid = threadIdx.x >> 5, lane = threadIdx.x & 31;
    int r = blockIdx.x * 8 + wid;
    float dcv = fabsf(decay[h]);
    const float* qrow = q + ((size_t)bh * T_ + r) * HS_;
    float q0 = qrow[lane], q1 = qrow[lane + 32];
    const float* kb = k + (size_t)bh * T_ * HS_;
    const float* vb = v + (size_t)bh * T_ * HS_;
    __shared__ float ks[32][64];
    __shared__ float vs[32][64];
    float mx = -1e30f, lsum = 0.f, a0 = 0.f, a1 = 0.f;
    int rmax = blockIdx.x * 8 + 7;
    for (int c0 = 0; c0 <= rmax; c0 += 32) {
        __syncthreads();
        for (int i = threadIdx.x; i < 32 * 16; i += 256) {
            int row = i >> 4, col4 = i & 15;
            ((float4*)ks[row])[col4] = ((const float4*)(kb + (size_t)(c0 + row) * HS_))[col4];
            ((float4*)vs[row])[col4] = ((const float4*)(vb + (size_t)(c0 + row) * HS_))[col4];
        }
        __syncthreads();
        int send = r - c0; if (send > 31) send = 31;
        for (int si = 0; si <= send; si++) {
            float sc = q0 * ks[si][lane] + q1 * ks[si][lane + 32];
            #pragma unroll
            for (int o = 16; o; o >>= 1) sc += __shfl_xor_sync(0xffffffffu, sc, o);
            int s = c0 + si;
            float xsc = sc * 0.125f + dcv * (float)(s - r);
            float nm  = fmaxf(mx, xsc);
            float esc = __expf(mx - nm);
            float e   = __expf(xsc - nm);
            lsum = lsum * esc + e;
            a0   = a0 * esc + e * vs[si][lane];
            a1   = a1 * esc + e * vs[si][lane + 32];
            mx = nm;
        }
    }
    float inv = 1.f / lsum;
    float* xr = x + ((size_t)(b * T_ + r)) * C_ + h * HS_;
    xr[lane]      += a0 * inv;
    xr[lane + 32] += a1 * inv;
}

// ---------------- SiLU gate -> fp16 ----------------
__global__ void gate_k() {
    int i = blockIdx.x * 256 + threadIdx.x;
    int m = i >> 10, j = i & 1023;
    float xv = g_hh[(size_t)m * HID_ + j];
    float xg = g_hh[(size_t)m * HID_ + 1024 + j];
    float sg = 1.f / (1.f + __expf(-xg));
    g_g16[i] = __float2half(xv * (xg * sg));
}

// ---------------- host launch ----------------
extern "C" void kernel_launch(void* const* d_in, const int* in_sizes, int n_in,
                              void* d_out, int out_size) {
    const int*   idx  = (const int*)  d_in[0];
    const float* tok  = (const float*)d_in[1];
    const float* pos  = (const float*)d_in[2];
    const float* Wq   = (const float*)d_in[3];
    const float* Wk   = (const float*)d_in[4];
    const float* Wv   = (const float*)d_in[5];
    const float* dcy  = (const float*)d_in[6];
    const float* ln1g = (const float*)d_in[7];
    const float* ln1b = (const float*)d_in[8];
    const float* fc1w = (const float*)d_in[9];
    const float* fc1b = (const float*)d_in[10];
    const float* fc2w = (const float*)d_in[11];
    const float* fc2b = (const float*)d_in[12];
    const float* ln2g = (const float*)d_in[13];
    const float* ln2b = (const float*)d_in[14];
    const float* lnfg = (const float*)d_in[15];
    const float* lnfb = (const float*)d_in[16];
    const float* lmw  = (const float*)d_in[17];
    float* out = (float*)d_out;

    __half *pwqkv, *pwfc1, *pwfc2, *pwlm, *ph16, *pg16;
    float *px, *pq, *pk, *pv, *phh;
    cudaGetSymbolAddress((void**)&px,    g_x);
    cudaGetSymbolAddress((void**)&ph16,  g_h16);
    cudaGetSymbolAddress((void**)&pq,    g_q);
    cudaGetSymbolAddress((void**)&pk,    g_k);
    cudaGetSymbolAddress((void**)&pv,    g_v);
    cudaGetSymbolAddress((void**)&phh,   g_hh);
    cudaGetSymbolAddress((void**)&pg16,  g_g16);
    cudaGetSymbolAddress((void**)&pwqkv, w_qkv16);
    cudaGetSymbolAddress((void**)&pwfc1, w_fc1);
    cudaGetSymbolAddress((void**)&pwfc2, w_fc2);
    cudaGetSymbolAddress((void**)&pwlm,  w_lm);

    // weight conversion (every launch; deterministic)
    { int n = L_*H_*C_*HS_;        qkvpack_k<<<(n + 255)/256, 256>>>(Wq, Wk, Wv); }
    { int n4 = (L_*C_*HID_)/4;     f2h4_k<<<(n4 + 255)/256, 256>>>(fc1w, pwfc1, n4); }
    { int n4 = (L_*(HID_/2)*C_)/4; f2h4_k<<<(n4 + 255)/256, 256>>>(fc2w, pwfc2, n4); }
    { int n4 = (C_*V_)/4;          f2h4_k<<<(n4 + 255)/256, 256>>>(lmw, pwlm, n4); }

    embed_k<<<BT_, 256>>>(idx, tok, pos);
    const int NQKV = 3*H_*HS_;   // 2304
    for (int l = 0; l < L_; l++) {
        ln_k<<<BT_, 256>>>(ln1g + l*C_, ln1b + l*C_);
        hgemm_k<3><<<dim3(NQKV/128, BT_/128), 256>>>(
            ph16, pwqkv + (size_t)l*C_*NQKV, nullptr, nullptr,
            BT_, NQKV, C_, pq, pk, pv);
        attn_k<<<dim3(T_/8, B_*H_), 256>>>(pq, pk, pv, dcy + l*H_, px);
        ln_k<<<BT_, 256>>>(ln2g + l*C_, ln2b + l*C_);
        hgemm_k<1><<<dim3(HID_/128, BT_/128), 256>>>(
            ph16, pwfc1 + (size_t)l*C_*HID_, phh, fc1b + l*HID_,
            BT_, HID_, C_, nullptr, nullptr, nullptr);
        gate_k<<<(BT_*(HID_/2))/256, 256>>>();
        hgemm_k<2><<<dim3(C_/128, BT_/128), 256>>>(
            pg16, pwfc2 + (size_t)l*(HID_/2)*C_, px, fc2b + l*C_,
            BT_, C_, HID_/2, nullptr, nullptr, nullptr);
    }
    ln_k<<<BT_, 256>>>(lnfg, lnfb);
    hgemm_k<0><<<dim3(V_/128, BT_/128), 256>>>(
        ph16, pwlm, out, nullptr, BT_, V_, C_, nullptr, nullptr, nullptr);
}

// round 5
// speedup vs baseline: 1.7148x; 1.0288x over previous
#include <cuda_runtime.h>
#include <cuda_fp16.h>
#include <cstdint>
#include <math.h>

#define L_ 4
#define H_ 12
#define C_ 768
#define HS_ 64
#define HID_ 2048
#define V_ 32000
#define B_ 2
#define T_ 2048
#define BT_ (B_*T_)

// ---------------- scratch (static device globals; no allocation) ----------------
__device__ float  g_x[BT_*C_];             // residual stream   [B*T, C] fp32
__device__ __half g_h16[BT_*C_];           // layernorm out fp16
__device__ float  g_q[B_*H_*T_*HS_];       // [B,H,T,HS] fp32 (attention path)
__device__ float  g_k[B_*H_*T_*HS_];
__device__ float  g_v[B_*H_*T_*HS_];
__device__ float  g_hh[(size_t)BT_*HID_];  // fc1 out fp32
__device__ __half g_g16[BT_*(HID_/2)];     // gated fp16
// fp16 weights (converted each launch; deterministic)
__device__ __half w_qkv16[(size_t)L_*C_*3*H_*HS_];   // [L][C][2304] packed q|k|v
__device__ __half w_fc1[(size_t)L_*C_*HID_];
__device__ __half w_fc2[(size_t)L_*(HID_/2)*C_];
__device__ __half w_lm[(size_t)C_*V_];

__device__ __forceinline__ unsigned int smem_u32(const void* p) {
    unsigned int a;
    asm("{ .reg .u64 t; cvta.to.shared.u64 t, %1; cvt.u32.u64 %0, t; }" : "=r"(a) : "l"(p));
    return a;
}
#define CP_ASYNC16(dst, src) \
    asm volatile("cp.async.cg.shared.global [%0], [%1], 16;" :: "r"(dst), "l"(src))
#define CP_COMMIT() asm volatile("cp.async.commit_group;")
#define CP_WAIT1()  asm volatile("cp.async.wait_group 1;")

// ---------------- fp32 -> fp16 bulk convert (vectorized) ----------------
__global__ void f2h4_k(const float* __restrict__ s, __half* __restrict__ d, int n4) {
    int i = blockIdx.x * 256 + threadIdx.x;
    if (i >= n4) return;
    float4 f = ((const float4*)s)[i];
    ((half2*)d)[2*i]     = __floats2half2_rn(f.x, f.y);
    ((half2*)d)[2*i + 1] = __floats2half2_rn(f.z, f.w);
}

// ---------------- pack Wq/Wk/Wv [L,H,C,HS] -> [L][C][3*H*HS] fp16 ----------------
__global__ void qkvpack_k(const float* __restrict__ Wq, const float* __restrict__ Wk,
                          const float* __restrict__ Wv) {
    int i = blockIdx.x * 256 + threadIdx.x;     // over L*H*C*HS
    if (i >= L_*H_*C_*HS_) return;
    int d = i % HS_; int tmp = i / HS_;
    int c = tmp % C_; tmp /= C_;
    int h = tmp % H_; int l = tmp / H_;
    size_t src = (((size_t)l*H_ + h)*C_ + c)*HS_ + d;
    size_t dst = ((size_t)l*C_ + c)*(3*H_*HS_) + h*HS_ + d;
    w_qkv16[dst           ] = __float2half(Wq[src]);
    w_qkv16[dst +   H_*HS_] = __float2half(Wk[src]);
    w_qkv16[dst + 2*H_*HS_] = __float2half(Wv[src]);
}

// ---------------- embedding ----------------
__global__ void embed_k(const int* __restrict__ idx,
                        const float* __restrict__ tok,
                        const float* __restrict__ pos) {
    int m = blockIdx.x;
    int t = m % T_;
    int id = idx[m];
    const float* tr = tok + (size_t)id * C_;
    const float* pr = pos + (size_t)t  * C_;
    float* xr = g_x + (size_t)m * C_;
    for (int c = threadIdx.x; c < C_; c += blockDim.x)
        xr[c] = tr[c] + pr[c];
}

// ---------------- layernorm -> fp16 ----------------
__global__ void ln_k(const float* __restrict__ gg, const float* __restrict__ bb) {
    int m = blockIdx.x;
    const float* row = g_x + (size_t)m * C_;
    float s = 0.f, s2 = 0.f;
    for (int c = threadIdx.x; c < C_; c += 256) {
        float v = row[c]; s += v; s2 += v * v;
    }
    #pragma unroll
    for (int o = 16; o; o >>= 1) {
        s  += __shfl_xor_sync(0xffffffffu, s,  o);
        s2 += __shfl_xor_sync(0xffffffffu, s2, o);
    }
    __shared__ float sh[16];
    int wid = threadIdx.x >> 5, lane = threadIdx.x & 31;
    if (lane == 0) { sh[wid] = s; sh[8 + wid] = s2; }
    __syncthreads();
    if (threadIdx.x == 0) {
        float ts = 0.f, ts2 = 0.f;
        #pragma unroll
        for (int w = 0; w < 8; w++) { ts += sh[w]; ts2 += sh[8 + w]; }
        sh[0] = ts; sh[8] = ts2;
    }
    __syncthreads();
    float mean = sh[0] * (1.f / C_);
    float var  = sh[8] * (1.f / C_) - mean * mean;
    float inv  = rsqrtf(var + 1e-5f);
    __half* orow = g_h16 + (size_t)m * C_;
    for (int c = threadIdx.x; c < 768; c += 256)
        orow[c] = __float2half((row[c] - mean) * inv * gg[c] + bb[c]);
}

// ---------------- HGEMM (cp.async double-buffered): C = A@B, fp32 accum ----------------
// EPI 0: C=acc   1: C=acc+bias   2: C+=acc+bias (residual)   3: QKV scatter to q/k/v
template<int EPI>
__global__ __launch_bounds__(256, 2)
void hgemm_k(const __half* __restrict__ A, const __half* __restrict__ Bw,
             float* __restrict__ C, const float* __restrict__ bias,
             int M, int N, int K,
             float* __restrict__ qo, float* __restrict__ ko, float* __restrict__ vo) {
    __shared__ __half As[2][128][40];    // m-major, k contiguous, pad 8
    __shared__ __half Bs[2][32][136];    // k-major, n contiguous, pad 8
    const int tid  = threadIdx.x;
    const int lane = tid & 31;
    const int wid  = tid >> 5;
    const int wm = (wid & 1) * 64;       // warp row offset (2 x 64)
    const int wn = (wid >> 1) * 32;      // warp col offset (4 x 32)
    const int m0 = blockIdx.y * 128;
    const int n0 = blockIdx.x * 128;

    float acc[4][4][4];
    #pragma unroll
    for (int i = 0; i < 4; i++)
        #pragma unroll
        for (int j = 0; j < 4; j++)
            acc[i][j][0] = acc[i][j][1] = acc[i][j][2] = acc[i][j][3] = 0.f;

    const int arow = tid >> 1, aseg = (tid & 1) * 16;  // A: 2 x 16B per thread
    const int brow = tid >> 3, bseg = (tid & 7) * 16;  // B: 2 x 16B per thread
    const __half* agp = A  + (size_t)(m0 + arow) * K + aseg;
    const __half* bgp = Bw + (size_t)brow * N + n0 + bseg;

    const int ntiles = K >> 5;
    // prologue: stage 0
    {
        unsigned da = smem_u32(&As[0][arow][aseg]);
        CP_ASYNC16(da,      agp);
        CP_ASYNC16(da + 16, agp + 8);
        unsigned db = smem_u32(&Bs[0][brow][bseg]);
        CP_ASYNC16(db,      bgp);
        CP_ASYNC16(db + 16, bgp + 8);
        CP_COMMIT();
    }
    for (int t = 0; t < ntiles; t++) {
        if (t + 1 < ntiles) {
            int s = (t + 1) & 1;
            const __half* ag = agp + (t + 1) * 32;
            const __half* bg = bgp + (size_t)(t + 1) * 32 * N;
            unsigned da = smem_u32(&As[s][arow][aseg]);
            CP_ASYNC16(da,      ag);
            CP_ASYNC16(da + 16, ag + 8);
            unsigned db = smem_u32(&Bs[s][brow][bseg]);
            CP_ASYNC16(db,      bg);
            CP_ASYNC16(db + 16, bg + 8);
        }
        CP_COMMIT();
        CP_WAIT1();
        __syncthreads();
        const int cs = t & 1;
        #pragma unroll
        for (int kk = 0; kk < 32; kk += 16) {
            unsigned int af[4][4], bf[4][2];
            #pragma unroll
            for (int i = 0; i < 4; i++) {
                unsigned int p = smem_u32(&As[cs][wm + i*16 + (lane & 7) + ((lane >> 3) & 1) * 8]
                                             [kk + (lane >> 4) * 8]);
                asm volatile("ldmatrix.sync.aligned.m8n8.x4.shared.b16 {%0,%1,%2,%3}, [%4];"
                             : "=r"(af[i][0]), "=r"(af[i][1]), "=r"(af[i][2]), "=r"(af[i][3])
                             : "r"(p));
            }
            #pragma unroll
            for (int jj = 0; jj < 2; jj++) {
                unsigned int p = smem_u32(&Bs[cs][kk + (lane & 15)]
                                             [wn + (lane >> 4) * 8 + jj * 16]);
                asm volatile("ldmatrix.sync.aligned.m8n8.x4.trans.shared.b16 {%0,%1,%2,%3}, [%4];"
                             : "=r"(bf[2*jj][0]), "=r"(bf[2*jj][1]),
                               "=r"(bf[2*jj+1][0]), "=r"(bf[2*jj+1][1])
                             : "r"(p));
            }
            #pragma unroll
            for (int i = 0; i < 4; i++)
                #pragma unroll
                for (int j = 0; j < 4; j++)
                    asm volatile(
                        "mma.sync.aligned.m16n8k16.row.col.f32.f16.f16.f32 "
                        "{%0,%1,%2,%3}, {%4,%5,%6,%7}, {%8,%9}, {%0,%1,%2,%3};"
                        : "+f"(acc[i][j][0]), "+f"(acc[i][j][1]),
                          "+f"(acc[i][j][2]), "+f"(acc[i][j][3])
                        : "r"(af[i][0]), "r"(af[i][1]), "r"(af[i][2]), "r"(af[i][3]),
                          "r"(bf[j][0]), "r"(bf[j][1]));
        }
        __syncthreads();
    }

    const int mrow = lane >> 2, ncol = (lane & 3) * 2;
    if (EPI == 3) {
        const int which = n0 / (H_*HS_);
        float* dst = (which == 0) ? qo : (which == 1) ? ko : vo;
        const int nbase = n0 - which * (H_*HS_);
        #pragma unroll
        for (int i = 0; i < 4; i++) {
            int m = m0 + wm + i*16 + mrow;
            int b = m >> 11, t = m & (T_-1);
            #pragma unroll
            for (int j = 0; j < 4; j++) {
                int r = nbase + wn + j*8 + ncol;
                int h = r >> 6, d = r & 63;
                size_t o = (((size_t)(b*H_ + h))*T_ + t)*HS_ + d;
                dst[o]           = acc[i][j][0];
                dst[o + 1]       = acc[i][j][1];
                dst[o + 8*HS_]   = acc[i][j][2];
                dst[o + 8*HS_+1] = acc[i][j][3];
            }
        }
    } else {
        #pragma unroll
        for (int i = 0; i < 4; i++) {
            int m = m0 + wm + i*16 + mrow;
            #pragma unroll
            for (int j = 0; j < 4; j++) {
                int n = n0 + wn + j*8 + ncol;
                size_t o = (size_t)m * N + n;
                float v0 = acc[i][j][0], v1 = acc[i][j][1];
                float v2 = acc[i][j][2], v3 = acc[i][j][3];
                if (EPI >= 1) { float b0 = bias[n], b1 = bias[n+1];
                                v0 += b0; v1 += b1; v2 += b0; v3 += b1; }
                if (EPI == 2) {
                    C[o]       += v0; C[o+1]       += v1;
                    C[o+8*(size_t)N] += v2; C[o+8*(size_t)N+1] += v3;
                } else {
                    C[o]       = v0; C[o+1]       = v1;
                    C[o+8*(size_t)N] = v2; C[o+8*(size_t)N+1] = v3;
                }
            }
        }
    }
}

// ---------------- fused causal attention (fp32, online softmax) ----------------
__global__ void attn_k(const float* __restrict__ q, const float* __restrict__ k,
                       const float* __restrict__ v, const float* __restrict__ decay,
                       float* __restrict__ x) {
    int bh = blockIdx.y;
    int b  = bh / H_, h = bh % H_;
    int wid = threadIdx.x >> 5, lane = threadIdx.x & 31;
    int r = blockIdx.x * 8 + wid;
    float dcv = fabsf(decay[h]);
    const float* qrow = q + ((size_t)bh * T_ + r) * HS_;
    float q0 = qrow[lane], q1 = qrow[lane + 32];
    const float* kb = k + (size_t)bh * T_ * HS_;
    const float* vb = v + (size_t)bh * T_ * HS_;
    __shared__ float ks[32][64];
    __shared__ float vs[32][64];
    float mx = -1e30f, lsum = 0.f, a0 = 0.f, a1 = 0.f;
    int rmax = blockIdx.x * 8 + 7;
    for (int c0 = 0; c0 <= rmax; c0 += 32) {
        __syncthreads();
        for (int i = threadIdx.x; i < 32 * 16; i += 256) {
            int row = i >> 4, col4 = i & 15;
            ((float4*)ks[row])[col4] = ((const float4*)(kb + (size_t)(c0 + row) * HS_))[col4];
            ((float4*)vs[row])[col4] = ((const float4*)(vb + (size_t)(c0 + row) * HS_))[col4];
        }
        __syncthreads();
        int send = r - c0; if (send > 31) send = 31;
        for (int si = 0; si <= send; si++) {
            float sc = q0 * ks[si][lane] + q1 * ks[si][lane + 32];
            #pragma unroll
            for (int o = 16; o; o >>= 1) sc += __shfl_xor_sync(0xffffffffu, sc, o);
            int s = c0 + si;
            float xsc = sc * 0.125f + dcv * (float)(s - r);
            float nm  = fmaxf(mx, xsc);
            float esc = __expf(mx - nm);
            float e   = __expf(xsc - nm);
            lsum = lsum * esc + e;
            a0   = a0 * esc + e * vs[si][lane];
            a1   = a1 * esc + e * vs[si][lane + 32];
            mx = nm;
        }
    }
    float inv = 1.f / lsum;
    float* xr = x + ((size_t)(b * T_ + r)) * C_ + h * HS_;
    xr[lane]      += a0 * inv;
    xr[lane + 32] += a1 * inv;
}

// ---------------- SiLU gate -> fp16 ----------------
__global__ void gate_k() {
    int i = blockIdx.x * 256 + threadIdx.x;
    int m = i >> 10, j = i & 1023;
    float xv = g_hh[(size_t)m * HID_ + j];
    float xg = g_hh[(size_t)m * HID_ + 1024 + j];
    float sg = 1.f / (1.f + __expf(-xg));
    g_g16[i] = __float2half(xv * (xg * sg));
}

// ---------------- host launch ----------------
extern "C" void kernel_launch(void* const* d_in, const int* in_sizes, int n_in,
                              void* d_out, int out_size) {
    const int*   idx  = (const int*)  d_in[0];
    const float* tok  = (const float*)d_in[1];
    const float* pos  = (const float*)d_in[2];
    const float* Wq   = (const float*)d_in[3];
    const float* Wk   = (const float*)d_in[4];
    const float* Wv   = (const float*)d_in[5];
    const float* dcy  = (const float*)d_in[6];
    const float* ln1g = (const float*)d_in[7];
    const float* ln1b = (const float*)d_in[8];
    const float* fc1w = (const float*)d_in[9];
    const float* fc1b = (const float*)d_in[10];
    const float* fc2w = (const float*)d_in[11];
    const float* fc2b = (const float*)d_in[12];
    const float* ln2g = (const float*)d_in[13];
    const float* ln2b = (const float*)d_in[14];
    const float* lnfg = (const float*)d_in[15];
    const float* lnfb = (const float*)d_in[16];
    const float* lmw  = (const float*)d_in[17];
    float* out = (float*)d_out;

    __half *pwqkv, *pwfc1, *pwfc2, *pwlm, *ph16, *pg16;
    float *px, *pq, *pk, *pv, *phh;
    cudaGetSymbolAddress((void**)&px,    g_x);
    cudaGetSymbolAddress((void**)&ph16,  g_h16);
    cudaGetSymbolAddress((void**)&pq,    g_q);
    cudaGetSymbolAddress((void**)&pk,    g_k);
    cudaGetSymbolAddress((void**)&pv,    g_v);
    cudaGetSymbolAddress((void**)&phh,   g_hh);
    cudaGetSymbolAddress((void**)&pg16,  g_g16);
    cudaGetSymbolAddress((void**)&pwqkv, w_qkv16);
    cudaGetSymbolAddress((void**)&pwfc1, w_fc1);
    cudaGetSymbolAddress((void**)&pwfc2, w_fc2);
    cudaGetSymbolAddress((void**)&pwlm,  w_lm);

    // weight conversion (every launch; deterministic)
    { int n = L_*H_*C_*HS_;        qkvpack_k<<<(n + 255)/256, 256>>>(Wq, Wk, Wv); }
    { int n4 = (L_*C_*HID_)/4;     f2h4_k<<<(n4 + 255)/256, 256>>>(fc1w, pwfc1, n4); }
    { int n4 = (L_*(HID_/2)*C_)/4; f2h4_k<<<(n4 + 255)/256, 256>>>(fc2w, pwfc2, n4); }
    { int n4 = (C_*V_)/4;          f2h4_k<<<(n4 + 255)/256, 256>>>(lmw, pwlm, n4); }

    embed_k<<<BT_, 256>>>(idx, tok, pos);
    const int NQKV = 3*H_*HS_;   // 2304
    for (int l = 0; l < L_; l++) {
        ln_k<<<BT_, 256>>>(ln1g + l*C_, ln1b + l*C_);
        hgemm_k<3><<<dim3(NQKV/128, BT_/128), 256>>>(
            ph16, pwqkv + (size_t)l*C_*NQKV, nullptr, nullptr,
            BT_, NQKV, C_, pq, pk, pv);
        attn_k<<<dim3(T_/8, B_*H_), 256>>>(pq, pk, pv, dcy + l*H_, px);
        ln_k<<<BT_, 256>>>(ln2g + l*C_, ln2b + l*C_);
        hgemm_k<1><<<dim3(HID_/128, BT_/128), 256>>>(
            ph16, pwfc1 + (size_t)l*C_*HID_, phh, fc1b + l*HID_,
            BT_, HID_, C_, nullptr, nullptr, nullptr);
        gate_k<<<(BT_*(HID_/2))/256, 256>>>();
        hgemm_k<2><<<dim3(C_/128, BT_/128), 256>>>(
            pg16, pwfc2 + (size_t)l*(HID_/2)*C_, px, fc2b + l*C_,
            BT_, C_, HID_/2, nullptr, nullptr, nullptr);
    }
    ln_k<<<BT_, 256>>>(lnfg, lnfb);
    hgemm_k<0><<<dim3(V_/128, BT_/128), 256>>>(
        ph16, pwlm, out, nullptr, BT_, V_, C_, nullptr, nullptr, nullptr);
}

// round 7
// speedup vs baseline: 1.7230x; 1.0048x over previous
#include <cuda_runtime.h>
#include <cuda_fp16.h>
#include <cstdint>
#include <math.h>

#define L_ 4
#define H_ 12
#define C_ 768
#define HS_ 64
#define HID_ 2048
#define V_ 32000
#define B_ 2
#define T_ 2048
#define BT_ (B_*T_)

// ---------------- scratch (static device globals; no allocation) ----------------
__device__ float  g_x[BT_*C_];             // residual stream [B*T, C] fp32
__device__ __half g_h16[BT_*C_];           // layernorm out fp16
__device__ float  g_q[B_*H_*T_*HS_];       // [B,H,T,HS] fp32
__device__ float  g_k[B_*H_*T_*HS_];
__device__ float  g_v[B_*H_*T_*HS_];
__device__ float  g_hh[(size_t)BT_*HID_];  // fc1 out fp32
__device__ __half g_g16[BT_*(HID_/2)];     // gated fp16
// fp16 weights [K][N] layout (converted per launch; deterministic)
__device__ __half w_qkv16[(size_t)L_*C_*3*H_*HS_];   // [L][768][2304]
__device__ __half w_fc1[(size_t)L_*C_*HID_];         // [L][768][2048]
__device__ __half w_fc2[(size_t)L_*(HID_/2)*C_];     // [L][1024][768]
__device__ __half w_lm[(size_t)C_*V_];               // [768][32000]

__device__ __forceinline__ unsigned smem_u32(const void* p) {
    unsigned a;
    asm("{ .reg .u64 t; cvta.to.shared.u64 t, %1; cvt.u32.u64 %0, t; }" : "=r"(a) : "l"(p));
    return a;
}
#define CP_ASYNC16(dst, src) \
    asm volatile("cp.async.cg.shared.global [%0], [%1], 16;" :: "r"(dst), "l"(src))
#define CP_COMMIT() asm volatile("cp.async.commit_group;")
#define CP_WAIT1()  asm volatile("cp.async.wait_group 1;" ::: "memory")

// ---------------- fp32 -> fp16 bulk convert (vectorized) ----------------
__global__ void f2h4_k(const float* __restrict__ s, __half* __restrict__ d, int n4) {
    int i = blockIdx.x * 256 + threadIdx.x;
    if (i >= n4) return;
    float4 f = ((const float4*)s)[i];
    ((half2*)d)[2*i]     = __floats2half2_rn(f.x, f.y);
    ((half2*)d)[2*i + 1] = __floats2half2_rn(f.z, f.w);
}

// ---------------- pack Wq/Wk/Wv [L,H,C,HS] -> [L][C][2304] fp16 ----------------
__global__ void qkvpack_k(const float* __restrict__ Wq, const float* __restrict__ Wk,
                          const float* __restrict__ Wv) {
    int i = blockIdx.x * 256 + threadIdx.x;     // over L*H*C*HS
    if (i >= L_*H_*C_*HS_) return;
    int d = i % HS_; int tmp = i / HS_;
    int c = tmp % C_; tmp /= C_;
    int h = tmp % H_; int l = tmp / H_;
    size_t src = (((size_t)l*H_ + h)*C_ + c)*HS_ + d;
    size_t dst = ((size_t)l*C_ + c)*(3*H_*HS_) + h*HS_ + d;
    w_qkv16[dst           ] = __float2half(Wq[src]);
    w_qkv16[dst +   H_*HS_] = __float2half(Wk[src]);
    w_qkv16[dst + 2*H_*HS_] = __float2half(Wv[src]);
}

// ---------------- embedding ----------------
__global__ void embed_k(const int* __restrict__ idx,
                        const float* __restrict__ tok,
                        const float* __restrict__ pos) {
    int m = blockIdx.x;
    int t = m % T_;
    int id = idx[m];
    const float* tr = tok + (size_t)id * C_;
    const float* pr = pos + (size_t)t  * C_;
    float* xr = g_x + (size_t)m * C_;
    for (int c = threadIdx.x; c < C_; c += blockDim.x)
        xr[c] = tr[c] + pr[c];
}

// ---------------- layernorm -> fp16 ----------------
__global__ void ln_k(const float* __restrict__ gg, const float* __restrict__ bb) {
    int m = blockIdx.x;
    const float* row = g_x + (size_t)m * C_;
    float s = 0.f, s2 = 0.f;
    for (int c = threadIdx.x; c < C_; c += 256) {
        float v = row[c]; s += v; s2 += v * v;
    }
    #pragma unroll
    for (int o = 16; o; o >>= 1) {
        s  += __shfl_xor_sync(0xffffffffu, s,  o);
        s2 += __shfl_xor_sync(0xffffffffu, s2, o);
    }
    __shared__ float sh[16];
    int wid = threadIdx.x >> 5, lane = threadIdx.x & 31;
    if (lane == 0) { sh[wid] = s; sh[8 + wid] = s2; }
    __syncthreads();
    if (threadIdx.x == 0) {
        float ts = 0.f, ts2 = 0.f;
        #pragma unroll
        for (int w = 0; w < 8; w++) { ts += sh[w]; ts2 += sh[8 + w]; }
        sh[0] = ts; sh[8] = ts2;
    }
    __syncthreads();
    float mean = sh[0] * (1.f / C_);
    float var  = sh[8] * (1.f / C_) - mean * mean;
    float inv  = rsqrtf(var + 1e-5f);
    __half* orow = g_h16 + (size_t)m * C_;
    for (int c = threadIdx.x; c < C_; c += 256)
        orow[c] = __float2half((row[c] - mean) * inv * gg[c] + bb[c]);
}

// ---------------- HGEMM v2: CTA 128x256, warp 64x64, k-chunk 64, 2-stage cp.async -------
// A[MxK] fp16 K-contig; B[KxN] fp16 N-contig; C fp32.
// EPI 0: C=acc   1: C=acc+bias   2: C+=acc+bias   3: QKV scatter
#define A_ROWB 144          // 72 halves per row (64 + pad 8)
#define B_ROWB 528          // 264 halves per row (256 + pad 8)
#define A_STG  18432        // 128 * 144
#define B_STG  33792        // 64 * 528
#define STG    (A_STG + B_STG)
#define SMEM2  (2 * STG)    // 104448

template<int EPI>
__global__ __launch_bounds__(256)
void hgemm2_k(const __half* __restrict__ A, const __half* __restrict__ Bw,
              float* __restrict__ C, const float* __restrict__ bias,
              int M, int N, int K,
              float* __restrict__ qo, float* __restrict__ ko, float* __restrict__ vo) {
    extern __shared__ char dsm[];
    const unsigned sb = smem_u32(dsm);
    const int tid  = threadIdx.x;
    const int lane = tid & 31;
    const int wid  = tid >> 5;
    const int wm = (wid & 1) * 64;     // 2 warps along m
    const int wn = (wid >> 1) * 64;    // 4 warps along n
    const int m0 = blockIdx.y * 128;
    const int n0 = blockIdx.x * 256;

    float acc[4][8][4];
    #pragma unroll
    for (int i = 0; i < 4; i++)
        #pragma unroll
        for (int j = 0; j < 8; j++)
            acc[i][j][0] = acc[i][j][1] = acc[i][j][2] = acc[i][j][3] = 0.f;

    const int nch = K >> 6;

    auto load_chunk = [&](int t) {
        const unsigned ab = sb + (t & 1) * STG;
        const unsigned bb = ab + A_STG;
        const int k0 = t << 6;
        // A: 128 rows x 8 segs (16B) = 1024 -> 4 per thread
        #pragma unroll
        for (int u = 0; u < 4; u++) {
            int idx = u * 256 + tid;
            int r = idx >> 3, sg = idx & 7;
            CP_ASYNC16(ab + r * A_ROWB + sg * 16,
                       A + (size_t)(m0 + r) * K + k0 + sg * 8);
        }
        // B: 64 rows x 32 segs = 2048 -> 8 per thread
        #pragma unroll
        for (int u = 0; u < 8; u++) {
            int idx = u * 256 + tid;
            int r = idx >> 5, sg = idx & 31;
            CP_ASYNC16(bb + r * B_ROWB + sg * 16,
                       Bw + (size_t)(k0 + r) * N + n0 + sg * 8);
        }
    };

    load_chunk(0);
    CP_COMMIT();

    for (int t = 0; t < nch; t++) {
        if (t + 1 < nch) load_chunk(t + 1);
        CP_COMMIT();
        CP_WAIT1();
        __syncthreads();
        const unsigned ab = sb + (t & 1) * STG;
        const unsigned bb = ab + A_STG;
        #pragma unroll
        for (int kk = 0; kk < 64; kk += 16) {
            unsigned af[4][4], bf[8][2];
            #pragma unroll
            for (int i = 0; i < 4; i++) {
                unsigned p = ab + (wm + i*16 + (lane & 15)) * A_ROWB
                                + (kk + (lane >> 4) * 8) * 2;
                asm volatile("ldmatrix.sync.aligned.m8n8.x4.shared.b16 {%0,%1,%2,%3}, [%4];"
                             : "=r"(af[i][0]), "=r"(af[i][1]), "=r"(af[i][2]), "=r"(af[i][3])
                             : "r"(p));
            }
            #pragma unroll
            for (int jj = 0; jj < 4; jj++) {
                unsigned p = bb + (kk + (lane & 15)) * B_ROWB
                                + (wn + (lane >> 4) * 8 + jj * 16) * 2;
                asm volatile("ldmatrix.sync.aligned.m8n8.x4.trans.shared.b16 {%0,%1,%2,%3}, [%4];"
                             : "=r"(bf[2*jj][0]), "=r"(bf[2*jj][1]),
                               "=r"(bf[2*jj+1][0]), "=r"(bf[2*jj+1][1])
                             : "r"(p));
            }
            #pragma unroll
            for (int i = 0; i < 4; i++)
                #pragma unroll
                for (int j = 0; j < 8; j++)
                    asm volatile(
                        "mma.sync.aligned.m16n8k16.row.col.f32.f16.f16.f32 "
                        "{%0,%1,%2,%3}, {%4,%5,%6,%7}, {%8,%9}, {%0,%1,%2,%3};"
                        : "+f"(acc[i][j][0]), "+f"(acc[i][j][1]),
                          "+f"(acc[i][j][2]), "+f"(acc[i][j][3])
                        : "r"(af[i][0]), "r"(af[i][1]), "r"(af[i][2]), "r"(af[i][3]),
                          "r"(bf[j][0]), "r"(bf[j][1]));
        }
        __syncthreads();
    }

    const int mrow = lane >> 2, ncol = (lane & 3) * 2;
    if (EPI == 3) {
        const int which = n0 / (H_*HS_);            // 256 | 768 boundaries align
        float* dst = (which == 0) ? qo : (which == 1) ? ko : vo;
        const int nbase = n0 - which * (H_*HS_);
        #pragma unroll
        for (int i = 0; i < 4; i++) {
            int m = m0 + wm + i*16 + mrow;
            int b = m >> 11, t = m & (T_-1);
            #pragma unroll
            for (int j = 0; j < 8; j++) {
                int r = nbase + wn + j*8 + ncol;
                int h = r >> 6, d = r & 63;
                size_t o = (((size_t)(b*H_ + h))*T_ + t)*HS_ + d;
                dst[o]           = acc[i][j][0];
                dst[o + 1]       = acc[i][j][1];
                dst[o + 8*HS_]   = acc[i][j][2];
                dst[o + 8*HS_+1] = acc[i][j][3];
            }
        }
    } else {
        #pragma unroll
        for (int i = 0; i < 4; i++) {
            int m = m0 + wm + i*16 + mrow;
            #pragma unroll
            for (int j = 0; j < 8; j++) {
                int n = n0 + wn + j*8 + ncol;
                size_t o = (size_t)m * N + n;
                float v0 = acc[i][j][0], v1 = acc[i][j][1];
                float v2 = acc[i][j][2], v3 = acc[i][j][3];
                if (EPI >= 1) { float b0 = bias[n], b1 = bias[n+1];
                                v0 += b0; v1 += b1; v2 += b0; v3 += b1; }
                if (EPI == 2) {
                    C[o]             += v0; C[o+1]             += v1;
                    C[o+8*(size_t)N] += v2; C[o+8*(size_t)N+1] += v3;
                } else {
                    C[o]             = v0; C[o+1]             = v1;
                    C[o+8*(size_t)N] = v2; C[o+8*(size_t)N+1] = v3;
                }
            }
        }
    }
}

// ---------------- fused causal attention (fp32, online softmax) ----------------
__global__ void attn_k(const float* __restrict__ q, const float* __restrict__ k,
                       const float* __restrict__ v, const float* __restrict__ decay,
                       float* __restrict__ x) {
    int bh = blockIdx.y;
    int b  = bh / H_, h = bh % H_;
    int wid = threadIdx.x >> 5, lane = threadIdx.x & 31;
    int r = blockIdx.x * 8 + wid;
    float dcv = fabsf(decay[h]);
    const float* qrow = q + ((size_t)bh * T_ + r) * HS_;
    float q0 = qrow[lane], q1 = qrow[lane + 32];
    const float* kb = k + (size_t)bh * T_ * HS_;
    const float* vb = v + (size_t)bh * T_ * HS_;
    __shared__ float ks[32][64];
    __shared__ float vs[32][64];
    float mx = -1e30f, lsum = 0.f, a0 = 0.f, a1 = 0.f;
    int rmax = blockIdx.x * 8 + 7;
    for (int c0 = 0; c0 <= rmax; c0 += 32) {
        __syncthreads();
        for (int i = threadIdx.x; i < 32 * 16; i += 256) {
            int row = i >> 4, col4 = i & 15;
            ((float4*)ks[row])[col4] = ((const float4*)(kb + (size_t)(c0 + row) * HS_))[col4];
            ((float4*)vs[row])[col4] = ((const float4*)(vb + (size_t)(c0 + row) * HS_))[col4];
        }
        __syncthreads();
        int send = r - c0; if (send > 31) send = 31;
        for (int si = 0; si <= send; si++) {
            float sc = q0 * ks[si][lane] + q1 * ks[si][lane + 32];
            #pragma unroll
            for (int o = 16; o; o >>= 1) sc += __shfl_xor_sync(0xffffffffu, sc, o);
            int s = c0 + si;
            float xsc = sc * 0.125f + dcv * (float)(s - r);
            float nm  = fmaxf(mx, xsc);
            float esc = __expf(mx - nm);
            float e   = __expf(xsc - nm);
            lsum = lsum * esc + e;
            a0   = a0 * esc + e * vs[si][lane];
            a1   = a1 * esc + e * vs[si][lane + 32];
            mx = nm;
        }
    }
    float inv = 1.f / lsum;
    float* xr = x + ((size_t)(b * T_ + r)) * C_ + h * HS_;
    xr[lane]      += a0 * inv;
    xr[lane + 32] += a1 * inv;
}

// ---------------- SiLU gate -> fp16 ----------------
__global__ void gate_k() {
    int i = blockIdx.x * 256 + threadIdx.x;
    int m = i >> 10, j = i & 1023;
    float xv = g_hh[(size_t)m * HID_ + j];
    float xg = g_hh[(size_t)m * HID_ + 1024 + j];
    float sg = 1.f / (1.f + __expf(-xg));
    g_g16[i] = __float2half(xv * (xg * sg));
}

// ---------------- host launch ----------------
extern "C" void kernel_launch(void* const* d_in, const int* in_sizes, int n_in,
                              void* d_out, int out_size) {
    const int*   idx  = (const int*)  d_in[0];
    const float* tok  = (const float*)d_in[1];
    const float* pos  = (const float*)d_in[2];
    const float* Wq   = (const float*)d_in[3];
    const float* Wk   = (const float*)d_in[4];
    const float* Wv   = (const float*)d_in[5];
    const float* dcy  = (const float*)d_in[6];
    const float* ln1g = (const float*)d_in[7];
    const float* ln1b = (const float*)d_in[8];
    const float* fc1w = (const float*)d_in[9];
    const float* fc1b = (const float*)d_in[10];
    const float* fc2w = (const float*)d_in[11];
    const float* fc2b = (const float*)d_in[12];
    const float* ln2g = (const float*)d_in[13];
    const float* ln2b = (const float*)d_in[14];
    const float* lnfg = (const float*)d_in[15];
    const float* lnfb = (const float*)d_in[16];
    const float* lmw  = (const float*)d_in[17];
    float* out = (float*)d_out;

    __half *pwqkv, *pwfc1, *pwfc2, *pwlm, *ph16, *pg16;
    float *px, *pq, *pk, *pv, *phh;
    cudaGetSymbolAddress((void**)&px,    g_x);
    cudaGetSymbolAddress((void**)&ph16,  g_h16);
    cudaGetSymbolAddress((void**)&pq,    g_q);
    cudaGetSymbolAddress((void**)&pk,    g_k);
    cudaGetSymbolAddress((void**)&pv,    g_v);
    cudaGetSymbolAddress((void**)&phh,   g_hh);
    cudaGetSymbolAddress((void**)&pg16,  g_g16);
    cudaGetSymbolAddress((void**)&pwqkv, w_qkv16);
    cudaGetSymbolAddress((void**)&pwfc1, w_fc1);
    cudaGetSymbolAddress((void**)&pwfc2, w_fc2);
    cudaGetSymbolAddress((void**)&pwlm,  w_lm);

    cudaFuncSetAttribute(hgemm2_k<0>, cudaFuncAttributeMaxDynamicSharedMemorySize, SMEM2);
    cudaFuncSetAttribute(hgemm2_k<1>, cudaFuncAttributeMaxDynamicSharedMemorySize, SMEM2);
    cudaFuncSetAttribute(hgemm2_k<2>, cudaFuncAttributeMaxDynamicSharedMemorySize, SMEM2);
    cudaFuncSetAttribute(hgemm2_k<3>, cudaFuncAttributeMaxDynamicSharedMemorySize, SMEM2);

    const int NQKV = 3*H_*HS_;   // 2304
    // order chosen so launch #4 (ncu capture slot) is the QKV GEMM
    { int n = L_*H_*C_*HS_; qkvpack_k<<<(n + 255)/256, 256>>>(Wq, Wk, Wv); }
    embed_k<<<BT_, 256>>>(idx, tok, pos);
    for (int l = 0; l < L_; l++) {
        ln_k<<<BT_, 256>>>(ln1g + l*C_, ln1b + l*C_);
        hgemm2_k<3><<<dim3(NQKV/256, BT_/128), 256, SMEM2>>>(
            ph16, pwqkv + (size_t)l*C_*NQKV, nullptr, nullptr,
            BT_, NQKV, C_, pq, pk, pv);
        attn_k<<<dim3(T_/8, B_*H_), 256>>>(pq, pk, pv, dcy + l*H_, px);
        ln_k<<<BT_, 256>>>(ln2g + l*C_, ln2b + l*C_);
        if (l == 0) { int n4 = (L_*C_*HID_)/4; f2h4_k<<<(n4 + 255)/256, 256>>>(fc1w, pwfc1, n4); }
        hgemm2_k<1><<<dim3(HID_/256, BT_/128), 256, SMEM2>>>(
            ph16, pwfc1 + (size_t)l*C_*HID_, phh, fc1b + l*HID_,
            BT_, HID_, C_, nullptr, nullptr, nullptr);
        gate_k<<<(BT_*(HID_/2))/256, 256>>>();
        if (l == 0) { int n4 = (L_*(HID_/2)*C_)/4; f2h4_k<<<(n4 + 255)/256, 256>>>(fc2w, pwfc2, n4); }
        hgemm2_k<2><<<dim3(C_/256, BT_/128), 256, SMEM2>>>(
            pg16, pwfc2 + (size_t)l*(HID_/2)*C_, px, fc2b + l*C_,
            BT_, C_, HID_/2, nullptr, nullptr, nullptr);
    }
    ln_k<<<BT_, 256>>>(lnfg, lnfb);
    { int n4 = (C_*V_)/4; f2h4_k<<<(n4 + 255)/256, 256>>>(lmw, pwlm, n4); }
    hgemm2_k<0><<<dim3(V_/256, BT_/128), 256, SMEM2>>>(
        ph16, pwlm, out, nullptr, BT_, V_, C_, nullptr, nullptr, nullptr);
}

// round 8
// speedup vs baseline: 9.8083x; 5.6924x over previous
#include <cuda_runtime.h>
#include <cuda_fp16.h>
#include <cstdint>
#include <math.h>

#define L_ 4
#define H_ 12
#define C_ 768
#define HS_ 64
#define HID_ 2048
#define V_ 32000
#define B_ 2
#define T_ 2048
#define BT_ (B_*T_)

// ---------------- scratch (static device globals; no allocation) ----------------
__device__ float  g_x[BT_*C_];             // residual stream [B*T, C] fp32
__device__ __half g_h16[BT_*C_];           // layernorm out fp16
__device__ __half g_q16[B_*H_*T_*HS_];     // [B,H,T,HS] fp16
__device__ __half g_k16[B_*H_*T_*HS_];
__device__ __half g_v16[B_*H_*T_*HS_];
__device__ float  g_hh[(size_t)BT_*HID_];  // fc1 out fp32
__device__ __half g_g16[BT_*(HID_/2)];     // gated fp16
// fp16 weights [K][N] layout (converted per launch; deterministic)
__device__ __half w_qkv16[(size_t)L_*C_*3*H_*HS_];   // [L][768][2304]
__device__ __half w_fc1[(size_t)L_*C_*HID_];         // [L][768][2048]
__device__ __half w_fc2[(size_t)L_*(HID_/2)*C_];     // [L][1024][768]
__device__ __half w_lm[(size_t)C_*V_];               // [768][32000]

__device__ __forceinline__ unsigned smem_u32(const void* p) {
    unsigned a;
    asm("{ .reg .u64 t; cvta.to.shared.u64 t, %1; cvt.u32.u64 %0, t; }" : "=r"(a) : "l"(p));
    return a;
}
#define CP_ASYNC16(dst, src) \
    asm volatile("cp.async.cg.shared.global [%0], [%1], 16;" :: "r"(dst), "l"(src))
#define CP_COMMIT() asm volatile("cp.async.commit_group;")
#define CP_WAIT1()  asm volatile("cp.async.wait_group 1;" ::: "memory")
#define CP_WAIT0()  asm volatile("cp.async.wait_group 0;" ::: "memory")

#define MMA16816(d, a, b0, b1) \
    asm volatile("mma.sync.aligned.m16n8k16.row.col.f32.f16.f16.f32 " \
        "{%0,%1,%2,%3}, {%4,%5,%6,%7}, {%8,%9}, {%0,%1,%2,%3};" \
        : "+f"((d)[0]), "+f"((d)[1]), "+f"((d)[2]), "+f"((d)[3]) \
        : "r"((a)[0]), "r"((a)[1]), "r"((a)[2]), "r"((a)[3]), "r"(b0), "r"(b1))

// ---------------- fp32 -> fp16 bulk convert ----------------
__global__ void f2h4_k(const float* __restrict__ s, __half* __restrict__ d, int n4) {
    int i = blockIdx.x * 256 + threadIdx.x;
    if (i >= n4) return;
    float4 f = ((const float4*)s)[i];
    ((half2*)d)[2*i]     = __floats2half2_rn(f.x, f.y);
    ((half2*)d)[2*i + 1] = __floats2half2_rn(f.z, f.w);
}

// ---------------- pack Wq/Wk/Wv [L,H,C,HS] -> [L][C][2304] fp16 ----------------
__global__ void qkvpack_k(const float* __restrict__ Wq, const float* __restrict__ Wk,
                          const float* __restrict__ Wv) {
    int i = blockIdx.x * 256 + threadIdx.x;
    if (i >= L_*H_*C_*HS_) return;
    int d = i % HS_; int tmp = i / HS_;
    int c = tmp % C_; tmp /= C_;
    int h = tmp % H_; int l = tmp / H_;
    size_t src = (((size_t)l*H_ + h)*C_ + c)*HS_ + d;
    size_t dst = ((size_t)l*C_ + c)*(3*H_*HS_) + h*HS_ + d;
    w_qkv16[dst           ] = __float2half(Wq[src]);
    w_qkv16[dst +   H_*HS_] = __float2half(Wk[src]);
    w_qkv16[dst + 2*H_*HS_] = __float2half(Wv[src]);
}

// ---------------- embedding ----------------
__global__ void embed_k(const int* __restrict__ idx,
                        const float* __restrict__ tok,
                        const float* __restrict__ pos) {
    int m = blockIdx.x;
    int t = m % T_;
    int id = idx[m];
    const float* tr = tok + (size_t)id * C_;
    const float* pr = pos + (size_t)t  * C_;
    float* xr = g_x + (size_t)m * C_;
    for (int c = threadIdx.x; c < C_; c += blockDim.x)
        xr[c] = tr[c] + pr[c];
}

// ---------------- layernorm -> fp16 ----------------
__global__ void ln_k(const float* __restrict__ gg, const float* __restrict__ bb) {
    int m = blockIdx.x;
    const float* row = g_x + (size_t)m * C_;
    float s = 0.f, s2 = 0.f;
    for (int c = threadIdx.x; c < C_; c += 256) {
        float v = row[c]; s += v; s2 += v * v;
    }
    #pragma unroll
    for (int o = 16; o; o >>= 1) {
        s  += __shfl_xor_sync(0xffffffffu, s,  o);
        s2 += __shfl_xor_sync(0xffffffffu, s2, o);
    }
    __shared__ float sh[16];
    int wid = threadIdx.x >> 5, lane = threadIdx.x & 31;
    if (lane == 0) { sh[wid] = s; sh[8 + wid] = s2; }
    __syncthreads();
    if (threadIdx.x == 0) {
        float ts = 0.f, ts2 = 0.f;
        #pragma unroll
        for (int w = 0; w < 8; w++) { ts += sh[w]; ts2 += sh[8 + w]; }
        sh[0] = ts; sh[8] = ts2;
    }
    __syncthreads();
    float mean = sh[0] * (1.f / C_);
    float var  = sh[8] * (1.f / C_) - mean * mean;
    float inv  = rsqrtf(var + 1e-5f);
    __half* orow = g_h16 + (size_t)m * C_;
    for (int c = threadIdx.x; c < C_; c += 256)
        orow[c] = __float2half((row[c] - mean) * inv * gg[c] + bb[c]);
}

// ---------------- HGEMM v2: CTA 128x256, warp 64x64, k-chunk 64, 2-stage cp.async -------
#define A_ROWB 144
#define B_ROWB 528
#define A_STG  18432
#define B_STG  33792
#define STG    (A_STG + B_STG)
#define SMEM2  (2 * STG)

template<int EPI>
__global__ __launch_bounds__(256)
void hgemm2_k(const __half* __restrict__ A, const __half* __restrict__ Bw,
              float* __restrict__ C, const float* __restrict__ bias,
              int M, int N, int K,
              __half* __restrict__ qo, __half* __restrict__ ko, __half* __restrict__ vo) {
    extern __shared__ char dsm[];
    const unsigned sb = smem_u32(dsm);
    const int tid  = threadIdx.x;
    const int lane = tid & 31;
    const int wid  = tid >> 5;
    const int wm = (wid & 1) * 64;
    const int wn = (wid >> 1) * 64;
    const int m0 = blockIdx.y * 128;
    const int n0 = blockIdx.x * 256;

    float acc[4][8][4];
    #pragma unroll
    for (int i = 0; i < 4; i++)
        #pragma unroll
        for (int j = 0; j < 8; j++)
            acc[i][j][0] = acc[i][j][1] = acc[i][j][2] = acc[i][j][3] = 0.f;

    const int nch = K >> 6;

    auto load_chunk = [&](int t) {
        const unsigned ab = sb + (t & 1) * STG;
        const unsigned bb = ab + A_STG;
        const int k0 = t << 6;
        #pragma unroll
        for (int u = 0; u < 4; u++) {
            int idx = u * 256 + tid;
            int r = idx >> 3, sg = idx & 7;
            CP_ASYNC16(ab + r * A_ROWB + sg * 16,
                       A + (size_t)(m0 + r) * K + k0 + sg * 8);
        }
        #pragma unroll
        for (int u = 0; u < 8; u++) {
            int idx = u * 256 + tid;
            int r = idx >> 5, sg = idx & 31;
            CP_ASYNC16(bb + r * B_ROWB + sg * 16,
                       Bw + (size_t)(k0 + r) * N + n0 + sg * 8);
        }
    };

    load_chunk(0);
    CP_COMMIT();

    for (int t = 0; t < nch; t++) {
        if (t + 1 < nch) load_chunk(t + 1);
        CP_COMMIT();
        CP_WAIT1();
        __syncthreads();
        const unsigned ab = sb + (t & 1) * STG;
        const unsigned bb = ab + A_STG;
        #pragma unroll
        for (int kk = 0; kk < 64; kk += 16) {
            unsigned af[4][4], bf[8][2];
            #pragma unroll
            for (int i = 0; i < 4; i++) {
                unsigned p = ab + (wm + i*16 + (lane & 15)) * A_ROWB
                                + (kk + (lane >> 4) * 8) * 2;
                asm volatile("ldmatrix.sync.aligned.m8n8.x4.shared.b16 {%0,%1,%2,%3}, [%4];"
                             : "=r"(af[i][0]), "=r"(af[i][1]), "=r"(af[i][2]), "=r"(af[i][3])
                             : "r"(p));
            }
            #pragma unroll
            for (int jj = 0; jj < 4; jj++) {
                unsigned p = bb + (kk + (lane & 15)) * B_ROWB
                                + (wn + (lane >> 4) * 8 + jj * 16) * 2;
                asm volatile("ldmatrix.sync.aligned.m8n8.x4.trans.shared.b16 {%0,%1,%2,%3}, [%4];"
                             : "=r"(bf[2*jj][0]), "=r"(bf[2*jj][1]),
                               "=r"(bf[2*jj+1][0]), "=r"(bf[2*jj+1][1])
                             : "r"(p));
            }
            #pragma unroll
            for (int i = 0; i < 4; i++)
                #pragma unroll
                for (int j = 0; j < 8; j++)
                    MMA16816(acc[i][j], af[i], bf[j][0], bf[j][1]);
        }
        __syncthreads();
    }

    const int mrow = lane >> 2, ncol = (lane & 3) * 2;
    if (EPI == 3) {
        const int which = n0 / (H_*HS_);
        __half* dst = (which == 0) ? qo : (which == 1) ? ko : vo;
        const int nbase = n0 - which * (H_*HS_);
        #pragma unroll
        for (int i = 0; i < 4; i++) {
            int m = m0 + wm + i*16 + mrow;
            int b = m >> 11, t = m & (T_-1);
            #pragma unroll
            for (int j = 0; j < 8; j++) {
                int r = nbase + wn + j*8 + ncol;
                int h = r >> 6, d = r & 63;
                size_t o = (((size_t)(b*H_ + h))*T_ + t)*HS_ + d;
                *(half2*)(dst + o) = __floats2half2_rn(acc[i][j][0], acc[i][j][1]);
                *(half2*)(dst + o + 8*HS_) = __floats2half2_rn(acc[i][j][2], acc[i][j][3]);
            }
        }
    } else {
        #pragma unroll
        for (int i = 0; i < 4; i++) {
            int m = m0 + wm + i*16 + mrow;
            #pragma unroll
            for (int j = 0; j < 8; j++) {
                int n = n0 + wn + j*8 + ncol;
                size_t o = (size_t)m * N + n;
                float v0 = acc[i][j][0], v1 = acc[i][j][1];
                float v2 = acc[i][j][2], v3 = acc[i][j][3];
                if (EPI >= 1) { float b0 = bias[n], b1 = bias[n+1];
                                v0 += b0; v1 += b1; v2 += b0; v3 += b1; }
                if (EPI == 2) {
                    C[o]             += v0; C[o+1]             += v1;
                    C[o+8*(size_t)N] += v2; C[o+8*(size_t)N+1] += v3;
                } else {
                    C[o]             = v0; C[o+1]             = v1;
                    C[o+8*(size_t)N] = v2; C[o+8*(size_t)N+1] = v3;
                }
            }
        }
    }
}

// ---------------- MMA flash attention: 64-query tile, 4 warps, online softmax ----------
// q/k/v fp16 [B,H,T,HS]; adds decay bias dcv*(s-r), causal; x += O (fp32 residual).
__global__ __launch_bounds__(128)
void fattn_k(const __half* __restrict__ q, const __half* __restrict__ k,
             const __half* __restrict__ v, const float* __restrict__ decay,
             float* __restrict__ x) {
    __shared__ __half Qs[64*72], Ks[64*72], Vs[64*72];
    const int bh = blockIdx.y, b = bh / H_, h = bh % H_;
    const int qt = gridDim.x - 1 - blockIdx.x;   // heavy tiles first
    const int q0 = qt * 64;
    const int tid = threadIdx.x, lane = tid & 31, wid = tid >> 5;
    const float dcv = fabsf(decay[h]);
    const __half* qb = q + ((size_t)bh * T_ + q0) * HS_;
    const __half* kb = k + (size_t)bh * T_ * HS_;
    const __half* vb = v + (size_t)bh * T_ * HS_;
    const unsigned sq = smem_u32(Qs), sk = smem_u32(Ks), sv = smem_u32(Vs);

    #pragma unroll
    for (int u = 0; u < 4; u++) {
        int idx = u * 128 + tid, r = idx >> 3, sg = idx & 7;
        CP_ASYNC16(sq + r * 144 + sg * 16, qb + (size_t)r * HS_ + sg * 8);
    }
    CP_COMMIT(); CP_WAIT0(); __syncthreads();

    unsigned aq[4][4];
    #pragma unroll
    for (int t = 0; t < 4; t++) {
        unsigned p = sq + (wid * 16 + (lane & 15)) * 144 + (t * 16 + (lane >> 4) * 8) * 2;
        asm volatile("ldmatrix.sync.aligned.m8n8.x4.shared.b16 {%0,%1,%2,%3}, [%4];"
                     : "=r"(aq[t][0]), "=r"(aq[t][1]), "=r"(aq[t][2]), "=r"(aq[t][3])
                     : "r"(p));
    }

    float m0 = -1e30f, m1 = -1e30f, l0 = 0.f, l1 = 0.f;
    float o[8][4] = {};
    const int row0 = q0 + wid * 16 + (lane >> 2);
    const int row1 = row0 + 8;

    for (int kt = 0; kt <= qt; kt++) {
        __syncthreads();
        #pragma unroll
        for (int u = 0; u < 4; u++) {
            int idx = u * 128 + tid, r = idx >> 3, sg = idx & 7;
            size_t go = (size_t)(kt * 64 + r) * HS_ + sg * 8;
            CP_ASYNC16(sk + r * 144 + sg * 16, kb + go);
            CP_ASYNC16(sv + r * 144 + sg * 16, vb + go);
        }
        CP_COMMIT(); CP_WAIT0(); __syncthreads();

        // S = Q K^T  (K tile is [key][hs] k-contiguous -> non-trans B frags)
        float s[8][4] = {};
        #pragma unroll
        for (int t = 0; t < 4; t++) {
            #pragma unroll
            for (int jj = 0; jj < 4; jj++) {
                unsigned bf[4];
                unsigned p = sk + (jj * 16 + ((lane >> 4) << 3) + (lane & 7)) * 144
                                + (t * 16 + ((lane >> 3) & 1) * 8) * 2;
                asm volatile("ldmatrix.sync.aligned.m8n8.x4.shared.b16 {%0,%1,%2,%3}, [%4];"
                             : "=r"(bf[0]), "=r"(bf[1]), "=r"(bf[2]), "=r"(bf[3])
                             : "r"(p));
                MMA16816(s[2*jj],   aq[t], bf[0], bf[1]);
                MMA16816(s[2*jj+1], aq[t], bf[2], bf[3]);
            }
        }

        // bias + causal mask
        const int colb = kt * 64 + (lane & 3) * 2;
        #pragma unroll
        for (int j = 0; j < 8; j++) {
            int c = colb + j * 8;
            s[j][0] = (c     <= row0) ? s[j][0]*0.125f + dcv*(float)(c     - row0) : -1e30f;
            s[j][1] = (c + 1 <= row0) ? s[j][1]*0.125f + dcv*(float)(c + 1 - row0) : -1e30f;
            s[j][2] = (c     <= row1) ? s[j][2]*0.125f + dcv*(float)(c     - row1) : -1e30f;
            s[j][3] = (c + 1 <= row1) ? s[j][3]*0.125f + dcv*(float)(c + 1 - row1) : -1e30f;
        }
        // row max (quad reduce)
        float rm0 = -1e30f, rm1 = -1e30f;
        #pragma unroll
        for (int j = 0; j < 8; j++) {
            rm0 = fmaxf(rm0, fmaxf(s[j][0], s[j][1]));
            rm1 = fmaxf(rm1, fmaxf(s[j][2], s[j][3]));
        }
        rm0 = fmaxf(rm0, __shfl_xor_sync(0xffffffffu, rm0, 1));
        rm0 = fmaxf(rm0, __shfl_xor_sync(0xffffffffu, rm0, 2));
        rm1 = fmaxf(rm1, __shfl_xor_sync(0xffffffffu, rm1, 1));
        rm1 = fmaxf(rm1, __shfl_xor_sync(0xffffffffu, rm1, 2));
        float mn0 = fmaxf(m0, rm0), mn1 = fmaxf(m1, rm1);
        float e0 = __expf(m0 - mn0), e1 = __expf(m1 - mn1);
        m0 = mn0; m1 = mn1;
        float rs0 = 0.f, rs1 = 0.f;
        #pragma unroll
        for (int j = 0; j < 8; j++) {
            s[j][0] = __expf(s[j][0] - m0);
            s[j][1] = __expf(s[j][1] - m0);
            s[j][2] = __expf(s[j][2] - m1);
            s[j][3] = __expf(s[j][3] - m1);
            rs0 += s[j][0] + s[j][1];
            rs1 += s[j][2] + s[j][3];
        }
        rs0 += __shfl_xor_sync(0xffffffffu, rs0, 1);
        rs0 += __shfl_xor_sync(0xffffffffu, rs0, 2);
        rs1 += __shfl_xor_sync(0xffffffffu, rs1, 1);
        rs1 += __shfl_xor_sync(0xffffffffu, rs1, 2);
        l0 = l0 * e0 + rs0;
        l1 = l1 * e1 + rs1;
        #pragma unroll
        for (int j = 0; j < 8; j++) {
            o[j][0] *= e0; o[j][1] *= e0; o[j][2] *= e1; o[j][3] *= e1;
        }
        // O += P V   (V tile [key][hs] n-contiguous -> trans B frags)
        #pragma unroll
        for (int t = 0; t < 4; t++) {
            unsigned pr[4];
            __half2 h0 = __floats2half2_rn(s[2*t][0],   s[2*t][1]);
            __half2 h1 = __floats2half2_rn(s[2*t][2],   s[2*t][3]);
            __half2 h2 = __floats2half2_rn(s[2*t+1][0], s[2*t+1][1]);
            __half2 h3 = __floats2half2_rn(s[2*t+1][2], s[2*t+1][3]);
            pr[0] = *(unsigned*)&h0; pr[1] = *(unsigned*)&h1;
            pr[2] = *(unsigned*)&h2; pr[3] = *(unsigned*)&h3;
            #pragma unroll
            for (int jj = 0; jj < 4; jj++) {
                unsigned vf[4];
                unsigned p = sv + (t * 16 + (lane & 15)) * 144
                                + ((lane >> 4) * 8 + jj * 16) * 2;
                asm volatile("ldmatrix.sync.aligned.m8n8.x4.trans.shared.b16 {%0,%1,%2,%3}, [%4];"
                             : "=r"(vf[0]), "=r"(vf[1]), "=r"(vf[2]), "=r"(vf[3])
                             : "r"(p));
                MMA16816(o[2*jj],   pr, vf[0], vf[1]);
                MMA16816(o[2*jj+1], pr, vf[2], vf[3]);
            }
        }
    }

    float i0 = 1.f / l0, i1 = 1.f / l1;
    float* xr0 = x + (size_t)(b * T_ + q0 + wid * 16 + (lane >> 2)) * C_ + h * HS_;
    float* xr1 = xr0 + 8 * C_;
    #pragma unroll
    for (int j = 0; j < 8; j++) {
        int c = j * 8 + (lane & 3) * 2;
        xr0[c]     += o[j][0] * i0;
        xr0[c + 1] += o[j][1] * i0;
        xr1[c]     += o[j][2] * i1;
        xr1[c + 1] += o[j][3] * i1;
    }
}

// ---------------- SiLU gate -> fp16 ----------------
__global__ void gate_k() {
    int i = blockIdx.x * 256 + threadIdx.x;
    int m = i >> 10, j = i & 1023;
    float xv = g_hh[(size_t)m * HID_ + j];
    float xg = g_hh[(size_t)m * HID_ + 1024 + j];
    float sg = 1.f / (1.f + __expf(-xg));
    g_g16[i] = __float2half(xv * (xg * sg));
}

// ---------------- host launch ----------------
extern "C" void kernel_launch(void* const* d_in, const int* in_sizes, int n_in,
                              void* d_out, int out_size) {
    const int*   idx  = (const int*)  d_in[0];
    const float* tok  = (const float*)d_in[1];
    const float* pos  = (const float*)d_in[2];
    const float* Wq   = (const float*)d_in[3];
    const float* Wk   = (const float*)d_in[4];
    const float* Wv   = (const float*)d_in[5];
    const float* dcy  = (const float*)d_in[6];
    const float* ln1g = (const float*)d_in[7];
    const float* ln1b = (const float*)d_in[8];
    const float* fc1w = (const float*)d_in[9];
    const float* fc1b = (const float*)d_in[10];
    const float* fc2w = (const float*)d_in[11];
    const float* fc2b = (const float*)d_in[12];
    const float* ln2g = (const float*)d_in[13];
    const float* ln2b = (const float*)d_in[14];
    const float* lnfg = (const float*)d_in[15];
    const float* lnfb = (const float*)d_in[16];
    const float* lmw  = (const float*)d_in[17];
    float* out = (float*)d_out;

    __half *pwqkv, *pwfc1, *pwfc2, *pwlm, *ph16, *pg16, *pq, *pk, *pv;
    float *px, *phh;
    cudaGetSymbolAddress((void**)&px,    g_x);
    cudaGetSymbolAddress((void**)&ph16,  g_h16);
    cudaGetSymbolAddress((void**)&pq,    g_q16);
    cudaGetSymbolAddress((void**)&pk,    g_k16);
    cudaGetSymbolAddress((void**)&pv,    g_v16);
    cudaGetSymbolAddress((void**)&phh,   g_hh);
    cudaGetSymbolAddress((void**)&pg16,  g_g16);
    cudaGetSymbolAddress((void**)&pwqkv, w_qkv16);
    cudaGetSymbolAddress((void**)&pwfc1, w_fc1);
    cudaGetSymbolAddress((void**)&pwfc2, w_fc2);
    cudaGetSymbolAddress((void**)&pwlm,  w_lm);

    cudaFuncSetAttribute(hgemm2_k<0>, cudaFuncAttributeMaxDynamicSharedMemorySize, SMEM2);
    cudaFuncSetAttribute(hgemm2_k<1>, cudaFuncAttributeMaxDynamicSharedMemorySize, SMEM2);
    cudaFuncSetAttribute(hgemm2_k<2>, cudaFuncAttributeMaxDynamicSharedMemorySize, SMEM2);
    cudaFuncSetAttribute(hgemm2_k<3>, cudaFuncAttributeMaxDynamicSharedMemorySize, SMEM2);

    const int NQKV = 3*H_*HS_;   // 2304
    { int n = L_*H_*C_*HS_; qkvpack_k<<<(n + 255)/256, 256>>>(Wq, Wk, Wv); }
    embed_k<<<BT_, 256>>>(idx, tok, pos);
    for (int l = 0; l < L_; l++) {
        ln_k<<<BT_, 256>>>(ln1g + l*C_, ln1b + l*C_);
        hgemm2_k<3><<<dim3(NQKV/256, BT_/128), 256, SMEM2>>>(
            ph16, pwqkv + (size_t)l*C_*NQKV, nullptr, nullptr,
            BT_, NQKV, C_, pq, pk, pv);
        fattn_k<<<dim3(T_/64, B_*H_), 128>>>(pq, pk, pv, dcy + l*H_, px);
        ln_k<<<BT_, 256>>>(ln2g + l*C_, ln2b + l*C_);
        if (l == 0) { int n4 = (L_*C_*HID_)/4; f2h4_k<<<(n4 + 255)/256, 256>>>(fc1w, pwfc1, n4); }
        hgemm2_k<1><<<dim3(HID_/256, BT_/128), 256, SMEM2>>>(
            ph16, pwfc1 + (size_t)l*C_*HID_, phh, fc1b + l*HID_,
            BT_, HID_, C_, nullptr, nullptr, nullptr);
        gate_k<<<(BT_*(HID_/2))/256, 256>>>();
        if (l == 0) { int n4 = (L_*(HID_/2)*C_)/4; f2h4_k<<<(n4 + 255)/256, 256>>>(fc2w, pwfc2, n4); }
        hgemm2_k<2><<<dim3(C_/256, BT_/128), 256, SMEM2>>>(
            pg16, pwfc2 + (size_t)l*(HID_/2)*C_, px, fc2b + l*C_,
            BT_, C_, HID_/2, nullptr, nullptr, nullptr);
    }
    ln_k<<<BT_, 256>>>(lnfg, lnfb);
    { int n4 = (C_*V_)/4; f2h4_k<<<(n4 + 255)/256, 256>>>(lmw, pwlm, n4); }
    hgemm2_k<0><<<dim3(V_/256, BT_/128), 256, SMEM2>>>(
        ph16, pwlm, out, nullptr, BT_, V_, C_, nullptr, nullptr, nullptr);
}